// round 1
// baseline (speedup 1.0000x reference)
#include <cuda_runtime.h>
#include <math.h>

#define CN 8192
#define CD 128
#define CV 3

#define TM 128
#define TN 64
#define KPAD 132          // 132*4B row stride -> LDS.128 across 16 lanes hits all 32 banks
#define MSPLIT 3
#define NTILES (CN / TM)  // 64
#define MTILES (CN / TN)  // 128

// ---- scratch (no allocations allowed) ----
__device__ __align__(256) float g_Hcn[CN * CD];
__device__ __align__(256) float g_Hvn[CV * CN * CD];
__device__ __align__(256) float g_denom[CV * CN];
__device__ double g_loss;

// packed dual-FMA: d.x += a.x*b.x ; d.y += a.y*b.y  (FFMA2, 2x scalar FFMA rate)
__device__ __forceinline__ void ffma2(float2& d, float2 a, float2 b) {
    unsigned long long& du = reinterpret_cast<unsigned long long&>(d);
    unsigned long long au = reinterpret_cast<unsigned long long&>(a);
    unsigned long long bu = reinterpret_cast<unsigned long long&>(b);
    asm("fma.rn.f32x2 %0, %1, %2, %0;" : "+l"(du) : "l"(au), "l"(bu));
}

// ---- kernel 0: zero accumulators ----
__global__ void sg_zero_kernel() {
    int i = blockIdx.x * blockDim.x + threadIdx.x;
    if (i < CV * CN) g_denom[i] = 0.0f;
    if (i == 0) g_loss = 0.0;
}

// ---- kernel 1: L2-normalize rows of Hc and Hv ----
__global__ void sg_normalize_kernel(const float* __restrict__ Hc,
                                    const float* __restrict__ Hv) {
    int row = blockIdx.x;  // 0 .. (CV+1)*CN - 1
    const float* src;
    float* dst;
    if (row < CN) {
        src = Hc + (size_t)row * CD;
        dst = g_Hcn + (size_t)row * CD;
    } else {
        src = Hv + (size_t)(row - CN) * CD;
        dst = g_Hvn + (size_t)(row - CN) * CD;
    }
    int t = threadIdx.x;  // 128 threads, one element each
    float x = src[t];
    float ss = x * x;
#pragma unroll
    for (int o = 16; o > 0; o >>= 1) ss += __shfl_xor_sync(0xffffffffu, ss, o);
    __shared__ float ws[4];
    if ((t & 31) == 0) ws[t >> 5] = ss;
    __syncthreads();
    float tot = ws[0] + ws[1] + ws[2] + ws[3];
    float nrm = sqrtf(tot);
    float invn = 1.0f / fmaxf(nrm, 1e-12f);
    dst[t] = x * invn;
}

// ---- kernel 2: fused sim-GEMM + exp + weighted denominator ----
// block: 256 threads (tx in [0,16), ty in [0,16))
// tile: TM=128 rows (n) x TN=64 cols (m), K = CD = 128 in one shot
// micro-tile: 8 n x 4 m per thread, float2 accs split by k-parity (f32x2 FMA)
__global__ __launch_bounds__(256, 1) void sg_main_kernel(const float* __restrict__ S) {
    extern __shared__ float smem[];
    float* As = smem;               // TM * KPAD
    float* Bs = smem + TM * KPAD;   // TN * KPAD

    const int t = threadIdx.x;
    const int tx = t & 15;
    const int ty = t >> 4;
    const int n0 = blockIdx.x * TM;
    const int v = blockIdx.y;
    const int ms = blockIdx.z;

    // load A tile (Hcn rows n0..n0+127), k-contiguous, float4
#pragma unroll
    for (int it = 0; it < (TM * CD / 4) / 256; ++it) {  // 16 iters
        int idx4 = it * 256 + t;
        int r = idx4 >> 5;            // 32 float4 per row
        int c = (idx4 & 31) << 2;
        *reinterpret_cast<float4*>(&As[r * KPAD + c]) =
            *reinterpret_cast<const float4*>(&g_Hcn[(size_t)(n0 + r) * CD + c]);
    }

    float denomAcc[8];
#pragma unroll
    for (int i = 0; i < 8; i++) denomAcc[i] = 0.0f;

    const float* Hvb = g_Hvn + (size_t)v * CN * CD;

    for (int mt = ms; mt < MTILES; mt += MSPLIT) {
        const int m0 = mt * TN;
        __syncthreads();  // protect Bs reuse (also covers As visibility on first iter)
#pragma unroll
        for (int it = 0; it < (TN * CD / 4) / 256; ++it) {  // 8 iters
            int idx4 = it * 256 + t;
            int r = idx4 >> 5;
            int c = (idx4 & 31) << 2;
            *reinterpret_cast<float4*>(&Bs[r * KPAD + c]) =
                *reinterpret_cast<const float4*>(&Hvb[(size_t)(m0 + r) * CD + c]);
        }
        __syncthreads();

        float2 acc[8][4];
#pragma unroll
        for (int i = 0; i < 8; i++)
#pragma unroll
            for (int j = 0; j < 4; j++) acc[i][j] = make_float2(0.0f, 0.0f);

#pragma unroll 8
        for (int k4 = 0; k4 < CD / 4; ++k4) {
            float4 a4[8], b4[4];
#pragma unroll
            for (int i = 0; i < 8; i++)
                a4[i] = *reinterpret_cast<const float4*>(&As[(ty + 16 * i) * KPAD + 4 * k4]);
#pragma unroll
            for (int j = 0; j < 4; j++)
                b4[j] = *reinterpret_cast<const float4*>(&Bs[(tx + 16 * j) * KPAD + 4 * k4]);
#pragma unroll
            for (int i = 0; i < 8; i++) {
#pragma unroll
                for (int j = 0; j < 4; j++) {
                    ffma2(acc[i][j], make_float2(a4[i].x, a4[i].y),
                          make_float2(b4[j].x, b4[j].y));
                    ffma2(acc[i][j], make_float2(a4[i].z, a4[i].w),
                          make_float2(b4[j].z, b4[j].w));
                }
            }
        }

        // epilogue: w = 1 - S[n,m]; denom += w * exp(sim / 0.5)
#pragma unroll
        for (int i = 0; i < 8; i++) {
            const int n = n0 + ty + 16 * i;
            const float* Srow = S + (size_t)n * CN + m0;
            float dsum = 0.0f;
#pragma unroll
            for (int j = 0; j < 4; j++) {
                float sim = acc[i][j].x + acc[i][j].y;
                float w = 1.0f - Srow[tx + 16 * j];
                dsum += w * __expf(sim * 2.0f);
            }
            denomAcc[i] += dsum;
        }
    }

    // reduce denom across tx (lane = (ty&1)*16 + tx, so xor 8..1 stays in tx-group)
#pragma unroll
    for (int i = 0; i < 8; i++) {
        float dv = denomAcc[i];
        dv += __shfl_xor_sync(0xffffffffu, dv, 8);
        dv += __shfl_xor_sync(0xffffffffu, dv, 4);
        dv += __shfl_xor_sync(0xffffffffu, dv, 2);
        dv += __shfl_xor_sync(0xffffffffu, dv, 1);
        if (tx == 0) atomicAdd(&g_denom[v * CN + n0 + ty + 16 * i], dv);
    }
}

// ---- kernel 3: positives (diagonal dots) + loss reduction ----
__global__ void sg_finalize_kernel() {
    int gwarp = (blockIdx.x * blockDim.x + threadIdx.x) >> 5;  // exactly CV*CN warps
    int lane = threadIdx.x & 31;
    int v = gwarp / CN;
    int n = gwarp % CN;
    const float* a = g_Hcn + (size_t)n * CD;
    const float* b = g_Hvn + (size_t)v * CN * CD + (size_t)n * CD;
    float s = 0.0f;
#pragma unroll
    for (int k = 0; k < CD / 32; k++) s += a[lane + 32 * k] * b[lane + 32 * k];
#pragma unroll
    for (int o = 16; o > 0; o >>= 1) s += __shfl_xor_sync(0xffffffffu, s, o);

    __shared__ double part[8];
    if (lane == 0) {
        float den = fmaxf(g_denom[gwarp], 1e-9f);
        // loss = -(positive - log(denom)), positive = sim_diag / T = 2*s
        part[threadIdx.x >> 5] = (double)(logf(den) - 2.0f * s);
    }
    __syncthreads();
    if (threadIdx.x == 0) {
        double bs = 0.0;
#pragma unroll
        for (int w = 0; w < 8; w++) bs += part[w];
        atomicAdd(&g_loss, bs);
    }
}

// ---- kernel 4: write scalar output ----
__global__ void sg_writeout_kernel(float* out) {
    out[0] = (float)(g_loss / (double)((long long)CN * CV));
}

extern "C" void kernel_launch(void* const* d_in, const int* in_sizes, int n_in,
                              void* d_out, int out_size) {
    const float* Hc = (const float*)d_in[0];
    const float* S = (const float*)d_in[1];
    const float* Hv = (const float*)d_in[2];
    float* out = (float*)d_out;

    const int smem_bytes = (TM + TN) * KPAD * (int)sizeof(float);  // ~101 KB
    cudaFuncSetAttribute(sg_main_kernel, cudaFuncAttributeMaxDynamicSharedMemorySize,
                         smem_bytes);

    sg_zero_kernel<<<(CV * CN + 255) / 256, 256>>>();
    sg_normalize_kernel<<<(CV + 1) * CN, 128>>>(Hc, Hv);
    dim3 grid(NTILES, CV, MSPLIT);
    sg_main_kernel<<<grid, 256, smem_bytes>>>(S);
    sg_finalize_kernel<<<(CV * CN) / 8, 256>>>();
    sg_writeout_kernel<<<1, 1>>>(out);
}

// round 3
// speedup vs baseline: 5.6597x; 5.6597x over previous
#include <cuda_runtime.h>
#include <cuda_fp16.h>
#include <math.h>
#include <cstdint>

#define CN 8192
#define CD 128
#define CV 3

#define TM 128            // n rows per CTA tile (MMA M)
#define TN 64             // m cols per tile (MMA N)
#define NTILES (CN / TM)  // 64
#define MTILES (CN / TN)  // 128
#define TOTAL_JOBS (NTILES * MTILES)  // 8192

// smem layout (bytes), padded row stride 272 = 136 halfs (17 x 16B chunks -> conflict-free ldmatrix)
#define RSTRIDE 272
#define A_OFF 0
#define A_BYTES (TM * RSTRIDE)                 // 34816
#define B_OFF A_BYTES
#define B_VIEW_BYTES (TN * RSTRIDE)            // 17408
#define B_BUF_BYTES (CV * B_VIEW_BYTES)        // 52224
#define SMEM_TOTAL (B_OFF + 2 * B_BUF_BYTES)   // 139264

// ---- device scratch (no allocations allowed) ----
__device__ __align__(256) __half g_Hc16[CN * CD];
__device__ __align__(256) __half g_Hv16[CV * CN * CD];
__device__ __align__(256) float g_denom[CV * CN];
__device__ double g_loss;

// ---------------- helpers ----------------
__device__ __forceinline__ uint32_t smem_u32(const void* p) {
    uint32_t a;
    asm("{ .reg .u64 t; cvta.to.shared.u64 t, %1; cvt.u32.u64 %0, t; }" : "=r"(a) : "l"(p));
    return a;
}
__device__ __forceinline__ void cp_async16(uint32_t dst, const void* src) {
    asm volatile("cp.async.cg.shared.global [%0], [%1], 16;" :: "r"(dst), "l"(src));
}
#define CP_COMMIT() asm volatile("cp.async.commit_group;" ::: "memory")
#define CP_WAIT0()  asm volatile("cp.async.wait_group 0;" ::: "memory")
#define CP_WAIT1()  asm volatile("cp.async.wait_group 1;" ::: "memory")

__device__ __forceinline__ void ldm4(uint32_t* r, uint32_t a) {
    asm volatile("ldmatrix.sync.aligned.m8n8.x4.shared.b16 {%0,%1,%2,%3}, [%4];"
                 : "=r"(r[0]), "=r"(r[1]), "=r"(r[2]), "=r"(r[3]) : "r"(a));
}
__device__ __forceinline__ void mma16816(float* c, const uint32_t* a, uint32_t b0, uint32_t b1) {
    asm volatile(
        "mma.sync.aligned.m16n8k16.row.col.f32.f16.f16.f32 "
        "{%0,%1,%2,%3}, {%4,%5,%6,%7}, {%8,%9}, {%0,%1,%2,%3};"
        : "+f"(c[0]), "+f"(c[1]), "+f"(c[2]), "+f"(c[3])
        : "r"(a[0]), "r"(a[1]), "r"(a[2]), "r"(a[3]), "r"(b0), "r"(b1));
}
__device__ __forceinline__ float ex2f(float x) {
    float r;
    asm("ex2.approx.f32 %0, %1;" : "=f"(r) : "f"(x));
    return r;
}
#define K2LOG2E 2.8853900817779268f  /* 2 / ln(2): exp(2*sim) = 2^(sim*K2) */

// ---- kernel 0: zero accumulators ----
__global__ void sg_zero_kernel() {
    int i = blockIdx.x * blockDim.x + threadIdx.x;
    if (i < CV * CN) g_denom[i] = 0.0f;
    if (i == 0) g_loss = 0.0;
}

// ---- kernel 1: L2-normalize rows of Hc and Hv -> fp16 ----
__global__ void sg_normalize_kernel(const float* __restrict__ Hc,
                                    const float* __restrict__ Hv) {
    int row = blockIdx.x;
    const float* src;
    __half* dst;
    if (row < CN) {
        src = Hc + (size_t)row * CD;
        dst = g_Hc16 + (size_t)row * CD;
    } else {
        src = Hv + (size_t)(row - CN) * CD;
        dst = g_Hv16 + (size_t)(row - CN) * CD;
    }
    int t = threadIdx.x;  // 128 threads
    float x = src[t];
    float ss = x * x;
#pragma unroll
    for (int o = 16; o > 0; o >>= 1) ss += __shfl_xor_sync(0xffffffffu, ss, o);
    __shared__ float ws[4];
    if ((t & 31) == 0) ws[t >> 5] = ss;
    __syncthreads();
    float tot = ws[0] + ws[1] + ws[2] + ws[3];
    float invn = 1.0f / fmaxf(sqrtf(tot), 1e-12f);
    dst[t] = __float2half_rn(x * invn);
}

// ---- smem tile loaders (cp.async, 16B chunks) ----
__device__ __forceinline__ void load_A(uint32_t sb, int n0, int t) {
#pragma unroll
    for (int k = 0; k < 8; k++) {
        int q = t + k * 256;            // 0..2047
        int r = q >> 4;                 // row 0..127
        int c = q & 15;                 // 16B chunk
        cp_async16(sb + A_OFF + r * RSTRIDE + c * 16,
                   g_Hc16 + (size_t)(n0 + r) * CD + c * 8);
    }
}
__device__ __forceinline__ void load_B(uint32_t sb, int buf, int m0, int t) {
    uint32_t base = sb + B_OFF + buf * B_BUF_BYTES;
#pragma unroll
    for (int k = 0; k < 12; k++) {
        int Q = t + k * 256;            // 0..3071
        int v = Q >> 10;
        int qq = Q & 1023;
        int r = qq >> 4;                // row 0..63
        int c = qq & 15;
        cp_async16(base + v * B_VIEW_BYTES + r * RSTRIDE + c * 16,
                   g_Hv16 + ((size_t)v * CN + (m0 + r)) * CD + c * 8);
    }
}

// ---- kernel 2: HMMA fused sim-GEMM + exp + weighted denominator ----
// persistent CTAs over flattened (ntile, mtile) jobs. 256 threads = 8 warps:
// warp grid 4(n) x 2(m); each warp computes 32n x 32m via m16n8k16.
__global__ __launch_bounds__(256, 1) void sg_main_kernel(const float* __restrict__ S) {
    extern __shared__ char smem[];
    uint32_t sb = smem_u32(smem);
    const int t = threadIdx.x;
    const int lane = t & 31;
    const int wid = t >> 5;
    const int wn = wid >> 1;     // 0..3 : n quarter
    const int wm = wid & 1;      // 0..1 : m half
    const int g = lane >> 3;
    const int lr = lane & 7;
    // per-lane ldmatrix address offsets (quadrant order matches mma frag order)
    const uint32_t aoff = (uint32_t)(((g & 1) * 8 + lr) * RSTRIDE + (g >> 1) * 16);
    const uint32_t boff = (uint32_t)(((g >> 1) * 8 + lr) * RSTRIDE + (g & 1) * 16);

    const int job0 = (int)(((long long)blockIdx.x * TOTAL_JOBS) / gridDim.x);
    const int job1 = (int)(((long long)(blockIdx.x + 1) * TOTAL_JOBS) / gridDim.x);

    int j = job0;
    while (j < job1) {
        const int nt = j >> 7;                 // 128 mtiles per ntile
        const int mt0 = j & 127;
        const int jend = min(job1, (nt + 1) << 7);
        const int nTi = jend - j;
        const int n0 = nt * TM;

        __syncthreads();  // previous segment fully done before overwriting A
        load_A(sb, n0, t);
        load_B(sb, 0, mt0 * TN, t);
        CP_COMMIT();

        uint32_t af[8][2][4];                  // A frags: 8 ksteps x 2 m16 tiles
        float denomAcc[CV][2][2];              // [view][mi][d8]
#pragma unroll
        for (int v = 0; v < CV; v++)
#pragma unroll
            for (int a = 0; a < 2; a++)
#pragma unroll
                for (int b = 0; b < 2; b++) denomAcc[v][a][b] = 0.0f;

        // per-thread S row offsets (4 rows owned by this thread)
        const int row_base = n0 + wn * 32 + (lane >> 2);
        const int col_base = wm * 32 + 2 * (lane & 3);

        for (int i = 0; i < nTi; i++) {
            const int p = i & 1;
            if (i + 1 < nTi) {
                load_B(sb, p ^ 1, (mt0 + i + 1) * TN, t);
                CP_COMMIT();
                CP_WAIT1();
            } else {
                CP_WAIT0();
            }
            __syncthreads();

            if (i == 0) {
                // load A fragments into registers (reused for the whole segment)
                uint32_t abase = sb + A_OFF + (uint32_t)(wn * 32) * RSTRIDE + aoff;
#pragma unroll
                for (int ks = 0; ks < 8; ks++)
#pragma unroll
                    for (int mi = 0; mi < 2; mi++)
                        ldm4(af[ks][mi], abase + mi * 16 * RSTRIDE + ks * 32);
            }

            const int m0 = (mt0 + i) * TN;
            // load S weights for this (thread x tile): 4 rows x 4 float2
            float2 wv[2][2][4];
#pragma unroll
            for (int mi = 0; mi < 2; mi++)
#pragma unroll
                for (int d8 = 0; d8 < 2; d8++) {
                    const float* rp = S + (size_t)(row_base + mi * 16 + 8 * d8) * CN +
                                      (m0 + col_base);
#pragma unroll
                    for (int ni = 0; ni < 4; ni++)
                        wv[mi][d8][ni] = *reinterpret_cast<const float2*>(rp + ni * 8);
                }

#pragma unroll
            for (int v = 0; v < CV; v++) {
                float acc[2][4][4];
#pragma unroll
                for (int mi = 0; mi < 2; mi++)
#pragma unroll
                    for (int ni = 0; ni < 4; ni++)
#pragma unroll
                        for (int c = 0; c < 4; c++) acc[mi][ni][c] = 0.0f;

                uint32_t bbase = sb + B_OFF + p * B_BUF_BYTES + v * B_VIEW_BYTES +
                                 (uint32_t)(wm * 32) * RSTRIDE + boff;
#pragma unroll
                for (int ks = 0; ks < 8; ks++) {
                    uint32_t bf0[4], bf1[4];
                    ldm4(bf0, bbase + ks * 32);                    // n-tiles 0,1
                    ldm4(bf1, bbase + 16 * RSTRIDE + ks * 32);     // n-tiles 2,3
#pragma unroll
                    for (int mi = 0; mi < 2; mi++) {
                        mma16816(acc[mi][0], af[ks][mi], bf0[0], bf0[1]);
                        mma16816(acc[mi][1], af[ks][mi], bf0[2], bf0[3]);
                        mma16816(acc[mi][2], af[ks][mi], bf1[0], bf1[1]);
                        mma16816(acc[mi][3], af[ks][mi], bf1[2], bf1[3]);
                    }
                }
                // epilogue: denom += (1 - S) * exp(2*sim)
#pragma unroll
                for (int mi = 0; mi < 2; mi++) {
                    float d0 = 0.0f, d1 = 0.0f;
#pragma unroll
                    for (int ni = 0; ni < 4; ni++) {
                        float2 w0 = wv[mi][0][ni];
                        float2 w1 = wv[mi][1][ni];
                        d0 = fmaf(1.0f - w0.x, ex2f(acc[mi][ni][0] * K2LOG2E), d0);
                        d0 = fmaf(1.0f - w0.y, ex2f(acc[mi][ni][1] * K2LOG2E), d0);
                        d1 = fmaf(1.0f - w1.x, ex2f(acc[mi][ni][2] * K2LOG2E), d1);
                        d1 = fmaf(1.0f - w1.y, ex2f(acc[mi][ni][3] * K2LOG2E), d1);
                    }
                    denomAcc[v][mi][0] += d0;
                    denomAcc[v][mi][1] += d1;
                }
            }
            __syncthreads();  // compute(i) done before next iter's load_B overwrites
        }

        // flush denominators for this segment (reduce over lane&3 = distinct cols)
#pragma unroll
        for (int v = 0; v < CV; v++)
#pragma unroll
            for (int mi = 0; mi < 2; mi++)
#pragma unroll
                for (int d8 = 0; d8 < 2; d8++) {
                    float val = denomAcc[v][mi][d8];
                    val += __shfl_xor_sync(0xffffffffu, val, 1);
                    val += __shfl_xor_sync(0xffffffffu, val, 2);
                    if ((lane & 3) == 0)
                        atomicAdd(&g_denom[v * CN + row_base + mi * 16 + 8 * d8], val);
                }
        j = jend;
    }
}

// ---- kernel 3: positives (diagonal dots, fp16-consistent) + loss reduction ----
__global__ void sg_finalize_kernel() {
    int gwarp = (blockIdx.x * blockDim.x + threadIdx.x) >> 5;  // CV*CN warps
    int lane = threadIdx.x & 31;
    int v = gwarp / CN;
    int n = gwarp % CN;
    const __half* a = g_Hc16 + (size_t)n * CD;
    const __half* b = g_Hv16 + (size_t)v * CN * CD + (size_t)n * CD;
    float s = 0.0f;
#pragma unroll
    for (int k = 0; k < CD / 32; k++)
        s += __half2float(a[lane + 32 * k]) * __half2float(b[lane + 32 * k]);
#pragma unroll
    for (int o = 16; o > 0; o >>= 1) s += __shfl_xor_sync(0xffffffffu, s, o);

    __shared__ double part[8];
    if (lane == 0) {
        float den = fmaxf(g_denom[gwarp], 1e-9f);
        part[threadIdx.x >> 5] = (double)(logf(den) - 2.0f * s);
    }
    __syncthreads();
    if (threadIdx.x == 0) {
        double bs = 0.0;
#pragma unroll
        for (int w = 0; w < 8; w++) bs += part[w];
        atomicAdd(&g_loss, bs);
    }
}

// ---- kernel 4: write scalar output ----
__global__ void sg_writeout_kernel(float* out) {
    out[0] = (float)(g_loss / (double)((long long)CN * CV));
}

extern "C" void kernel_launch(void* const* d_in, const int* in_sizes, int n_in,
                              void* d_out, int out_size) {
    const float* Hc = (const float*)d_in[0];
    const float* S = (const float*)d_in[1];
    const float* Hv = (const float*)d_in[2];
    float* out = (float*)d_out;

    int nsm = 148;
    cudaDeviceGetAttribute(&nsm, cudaDevAttrMultiProcessorCount, 0);

    cudaFuncSetAttribute(sg_main_kernel, cudaFuncAttributeMaxDynamicSharedMemorySize,
                         SMEM_TOTAL);

    sg_zero_kernel<<<(CV * CN + 255) / 256, 256>>>();
    sg_normalize_kernel<<<(CV + 1) * CN, 128>>>(Hc, Hv);
    sg_main_kernel<<<nsm, 256, SMEM_TOTAL>>>(S);
    sg_finalize_kernel<<<(CV * CN) / 8, 256>>>();
    sg_writeout_kernel<<<1, 1>>>(out);
}

// round 4
// speedup vs baseline: 6.7190x; 1.1872x over previous
#include <cuda_runtime.h>
#include <cuda_fp16.h>
#include <math.h>
#include <cstdint>

#define CN 8192
#define CD 128
#define CV 3

#define TM 128            // n rows per CTA tile (MMA M)
#define TN 64             // m cols per tile (MMA N)
#define NTILES (CN / TM)  // 64
#define MTILES (CN / TN)  // 128
#define TOTAL_JOBS (NTILES * MTILES)  // 8192

#define RSTRIDE 272       // padded row stride (bytes): conflict-free ldmatrix
#define A_OFF 0
#define A_BYTES (TM * RSTRIDE)                 // 34816
#define B_OFF A_BYTES
#define B_VIEW_BYTES (TN * RSTRIDE)            // 17408
#define B_BUF_BYTES (CV * B_VIEW_BYTES)        // 52224
#define NBUF 3
#define SMEM_TOTAL (B_OFF + NBUF * B_BUF_BYTES)  // 191488

#define K2LOG2E 2.8853900817779268  /* 2/ln2 : exp(2*sim) = 2^(sim*K2) */
#define LN2F 0.6931471805599453f

// ---- device scratch ----
__device__ __align__(256) __half g_Hc16[CN * CD];   // pre-scaled by K2LOG2E
__device__ __align__(256) __half g_Hv16[CV * CN * CD];
__device__ __align__(256) float g_denom[CV * CN];
__device__ double g_loss;

// ---------------- helpers ----------------
__device__ __forceinline__ uint32_t smem_u32(const void* p) {
    uint32_t a;
    asm("{ .reg .u64 t; cvta.to.shared.u64 t, %1; cvt.u32.u64 %0, t; }" : "=r"(a) : "l"(p));
    return a;
}
__device__ __forceinline__ void cp_async16(uint32_t dst, const void* src) {
    asm volatile("cp.async.cg.shared.global [%0], [%1], 16;" :: "r"(dst), "l"(src));
}
#define CP_COMMIT() asm volatile("cp.async.commit_group;" ::: "memory")
#define CP_WAIT0()  asm volatile("cp.async.wait_group 0;" ::: "memory")
#define CP_WAIT1()  asm volatile("cp.async.wait_group 1;" ::: "memory")

__device__ __forceinline__ void ldm4(uint32_t* r, uint32_t a) {
    asm volatile("ldmatrix.sync.aligned.m8n8.x4.shared.b16 {%0,%1,%2,%3}, [%4];"
                 : "=r"(r[0]), "=r"(r[1]), "=r"(r[2]), "=r"(r[3]) : "r"(a));
}
// fp16-accumulate HMMA
__device__ __forceinline__ void mma16816h(uint32_t* c, const uint32_t* a, uint32_t b0, uint32_t b1) {
    asm volatile(
        "mma.sync.aligned.m16n8k16.row.col.f16.f16.f16.f16 "
        "{%0,%1}, {%2,%3,%4,%5}, {%6,%7}, {%0,%1};"
        : "+r"(c[0]), "+r"(c[1])
        : "r"(a[0]), "r"(a[1]), "r"(a[2]), "r"(a[3]), "r"(b0), "r"(b1));
}
__device__ __forceinline__ uint32_t ex2h2(uint32_t x) {
    uint32_t r;
    asm("ex2.approx.f16x2 %0, %1;" : "=r"(r) : "r"(x));
    return r;
}

// ---- kernel 0: zero accumulators ----
__global__ void sg_zero_kernel() {
    int i = blockIdx.x * blockDim.x + threadIdx.x;
    if (i < CV * CN) g_denom[i] = 0.0f;
    if (i == 0) g_loss = 0.0;
}

// ---- kernel 1: L2-normalize rows -> fp16 (Hc pre-scaled by 2/ln2) ----
__global__ void sg_normalize_kernel(const float* __restrict__ Hc,
                                    const float* __restrict__ Hv) {
    int row = blockIdx.x;
    const float* src;
    __half* dst;
    float scale;
    if (row < CN) {
        src = Hc + (size_t)row * CD;
        dst = g_Hc16 + (size_t)row * CD;
        scale = (float)K2LOG2E;
    } else {
        src = Hv + (size_t)(row - CN) * CD;
        dst = g_Hv16 + (size_t)(row - CN) * CD;
        scale = 1.0f;
    }
    int t = threadIdx.x;  // 128 threads
    float x = src[t];
    float ss = x * x;
#pragma unroll
    for (int o = 16; o > 0; o >>= 1) ss += __shfl_xor_sync(0xffffffffu, ss, o);
    __shared__ float ws[4];
    if ((t & 31) == 0) ws[t >> 5] = ss;
    __syncthreads();
    float tot = ws[0] + ws[1] + ws[2] + ws[3];
    float invn = scale / fmaxf(sqrtf(tot), 1e-12f);
    dst[t] = __float2half_rn(x * invn);
}

// ---- smem tile loaders ----
__device__ __forceinline__ void load_A(uint32_t sb, int n0, int t) {
#pragma unroll
    for (int k = 0; k < 8; k++) {
        int q = t + k * 256;
        int r = q >> 4;
        int c = q & 15;
        cp_async16(sb + A_OFF + r * RSTRIDE + c * 16,
                   g_Hc16 + (size_t)(n0 + r) * CD + c * 8);
    }
}
__device__ __forceinline__ void load_B(uint32_t sb, int buf, int m0, int t) {
    uint32_t base = sb + B_OFF + buf * B_BUF_BYTES;
#pragma unroll
    for (int k = 0; k < 12; k++) {
        int Q = t + k * 256;
        int v = Q >> 10;
        int qq = Q & 1023;
        int r = qq >> 4;
        int c = qq & 15;
        cp_async16(base + v * B_VIEW_BYTES + r * RSTRIDE + c * 16,
                   g_Hv16 + ((size_t)v * CN + (m0 + r)) * CD + c * 8);
    }
}

// ---- kernel 2: HMMA(f16-acc) fused GEMM + exp + weighted denom ----
__global__ __launch_bounds__(256, 1) void sg_main_kernel(const float* __restrict__ S) {
    extern __shared__ char smem[];
    uint32_t sb = smem_u32(smem);
    const int t = threadIdx.x;
    const int lane = t & 31;
    const int wid = t >> 5;
    const int wn = wid >> 1;     // 0..3 : n quarter
    const int wm = wid & 1;      // 0..1 : m half
    const int g = lane >> 3;
    const int lr = lane & 7;
    const uint32_t aoff = (uint32_t)(((g & 1) * 8 + lr) * RSTRIDE + (g >> 1) * 16);
    const uint32_t boff = (uint32_t)(((g >> 1) * 8 + lr) * RSTRIDE + (g & 1) * 16);

    const int job0 = (int)(((long long)blockIdx.x * TOTAL_JOBS) / gridDim.x);
    const int job1 = (int)(((long long)(blockIdx.x + 1) * TOTAL_JOBS) / gridDim.x);

    int j = job0;
    while (j < job1) {
        const int nt = j >> 7;
        const int mt0 = j & 127;
        const int jend = min(job1, (nt + 1) << 7);
        const int nTi = jend - j;
        const int n0 = nt * TM;

        __syncthreads();  // previous segment fully done before overwriting smem
        load_A(sb, n0, t);
        load_B(sb, 0, mt0 * TN, t);
        CP_COMMIT();
        if (nTi > 1) { load_B(sb, 1, (mt0 + 1) * TN, t); }
        CP_COMMIT();   // commit (possibly empty) so group count is uniform

        uint32_t af[8][2][4];
        float denomAcc[CV][2][2];
#pragma unroll
        for (int v = 0; v < CV; v++)
#pragma unroll
            for (int a = 0; a < 2; a++)
#pragma unroll
                for (int b = 0; b < 2; b++) denomAcc[v][a][b] = 0.0f;

        const int row_base = n0 + wn * 32 + (lane >> 2);
        const int col_base = wm * 32 + 2 * (lane & 3);

        int buf = 0;  // buf index of tile i (mod 3)
        for (int i = 0; i < nTi; i++) {
            if (i + 1 < nTi) CP_WAIT1(); else CP_WAIT0();
            __syncthreads();  // B(i) visible to all; compute(i-1) done everywhere

            // issue load for tile i+2 into buf (i+2)%3 (freed by compute(i-1))
            int nbuf = buf + 2; if (nbuf >= 3) nbuf -= 3;
            if (i + 2 < nTi) { load_B(sb, nbuf, (mt0 + i + 2) * TN, t); CP_COMMIT(); }

            if (i == 0) {
                uint32_t abase = sb + A_OFF + (uint32_t)(wn * 32) * RSTRIDE + aoff;
#pragma unroll
                for (int ks = 0; ks < 8; ks++)
#pragma unroll
                    for (int mi = 0; mi < 2; mi++)
                        ldm4(af[ks][mi], abase + mi * 16 * RSTRIDE + ks * 32);
            }

            const int m0 = (mt0 + i) * TN;
            // preload (1 - S) weights: 4 rows x 4 float2 per thread
            float2 wv[2][2][4];
#pragma unroll
            for (int mi = 0; mi < 2; mi++)
#pragma unroll
                for (int d8 = 0; d8 < 2; d8++) {
                    const float* rp = S + (size_t)(row_base + mi * 16 + 8 * d8) * CN +
                                      (m0 + col_base);
#pragma unroll
                    for (int ni = 0; ni < 4; ni++) {
                        float2 x = *reinterpret_cast<const float2*>(rp + ni * 8);
                        wv[mi][d8][ni] = make_float2(1.0f - x.x, 1.0f - x.y);
                    }
                }

#pragma unroll
            for (int v = 0; v < CV; v++) {
                uint32_t acc[2][4][2];  // [mi][ni][row-octet], f16x2 cols (2c,2c+1)
#pragma unroll
                for (int mi = 0; mi < 2; mi++)
#pragma unroll
                    for (int ni = 0; ni < 4; ni++) {
                        acc[mi][ni][0] = 0u; acc[mi][ni][1] = 0u;
                    }

                uint32_t bbase = sb + B_OFF + buf * B_BUF_BYTES + v * B_VIEW_BYTES +
                                 (uint32_t)(wm * 32) * RSTRIDE + boff;
#pragma unroll
                for (int ks = 0; ks < 8; ks++) {
                    uint32_t bf0[4], bf1[4];
                    ldm4(bf0, bbase + ks * 32);
                    ldm4(bf1, bbase + 16 * RSTRIDE + ks * 32);
#pragma unroll
                    for (int mi = 0; mi < 2; mi++) {
                        mma16816h(acc[mi][0], af[ks][mi], bf0[0], bf0[1]);
                        mma16816h(acc[mi][1], af[ks][mi], bf0[2], bf0[3]);
                        mma16816h(acc[mi][2], af[ks][mi], bf1[0], bf1[1]);
                        mma16816h(acc[mi][3], af[ks][mi], bf1[2], bf1[3]);
                    }
                }
                // epilogue: acc already holds log2(exp(2*sim)); denom += w * 2^acc
#pragma unroll
                for (int mi = 0; mi < 2; mi++) {
                    float d0 = 0.0f, d1 = 0.0f;
#pragma unroll
                    for (int ni = 0; ni < 4; ni++) {
                        uint32_t e0 = ex2h2(acc[mi][ni][0]);
                        uint32_t e1 = ex2h2(acc[mi][ni][1]);
                        float2 f0 = __half22float2(*reinterpret_cast<__half2*>(&e0));
                        float2 f1 = __half22float2(*reinterpret_cast<__half2*>(&e1));
                        float2 w0 = wv[mi][0][ni];
                        float2 w1 = wv[mi][1][ni];
                        d0 = fmaf(w0.x, f0.x, d0);
                        d0 = fmaf(w0.y, f0.y, d0);
                        d1 = fmaf(w1.x, f1.x, d1);
                        d1 = fmaf(w1.y, f1.y, d1);
                    }
                    denomAcc[v][mi][0] += d0;
                    denomAcc[v][mi][1] += d1;
                }
            }
            buf++; if (buf >= 3) buf -= 3;
        }

        // flush denominators (reduce over lane&3 = distinct col groups)
#pragma unroll
        for (int v = 0; v < CV; v++)
#pragma unroll
            for (int mi = 0; mi < 2; mi++)
#pragma unroll
                for (int d8 = 0; d8 < 2; d8++) {
                    float val = denomAcc[v][mi][d8];
                    val += __shfl_xor_sync(0xffffffffu, val, 1);
                    val += __shfl_xor_sync(0xffffffffu, val, 2);
                    if ((lane & 3) == 0)
                        atomicAdd(&g_denom[v * CN + row_base + mi * 16 + 8 * d8], val);
                }
        j = jend;
    }
}

// ---- kernel 3: positives + loss reduction ----
// g_Hc16 is pre-scaled by 2/ln2, so positive = 2*sim = (scaled dot) * ln2
__global__ void sg_finalize_kernel() {
    int gwarp = (blockIdx.x * blockDim.x + threadIdx.x) >> 5;
    int lane = threadIdx.x & 31;
    int v = gwarp / CN;
    int n = gwarp % CN;
    const __half* a = g_Hc16 + (size_t)n * CD;
    const __half* b = g_Hv16 + (size_t)v * CN * CD + (size_t)n * CD;
    float s = 0.0f;
#pragma unroll
    for (int k = 0; k < CD / 32; k++)
        s += __half2float(a[lane + 32 * k]) * __half2float(b[lane + 32 * k]);
#pragma unroll
    for (int o = 16; o > 0; o >>= 1) s += __shfl_xor_sync(0xffffffffu, s, o);

    __shared__ double part[8];
    if (lane == 0) {
        float den = fmaxf(g_denom[gwarp], 1e-9f);
        part[threadIdx.x >> 5] = (double)(logf(den) - s * LN2F);
    }
    __syncthreads();
    if (threadIdx.x == 0) {
        double bs = 0.0;
#pragma unroll
        for (int w = 0; w < 8; w++) bs += part[w];
        atomicAdd(&g_loss, bs);
    }
}

// ---- kernel 4: write scalar output ----
__global__ void sg_writeout_kernel(float* out) {
    out[0] = (float)(g_loss / (double)((long long)CN * CV));
}

extern "C" void kernel_launch(void* const* d_in, const int* in_sizes, int n_in,
                              void* d_out, int out_size) {
    const float* Hc = (const float*)d_in[0];
    const float* S = (const float*)d_in[1];
    const float* Hv = (const float*)d_in[2];
    float* out = (float*)d_out;

    int nsm = 148;
    cudaDeviceGetAttribute(&nsm, cudaDevAttrMultiProcessorCount, 0);

    cudaFuncSetAttribute(sg_main_kernel, cudaFuncAttributeMaxDynamicSharedMemorySize,
                         SMEM_TOTAL);

    sg_zero_kernel<<<(CV * CN + 255) / 256, 256>>>();
    sg_normalize_kernel<<<(CV + 1) * CN, 128>>>(Hc, Hv);
    sg_main_kernel<<<nsm, 256, SMEM_TOTAL>>>(S);
    sg_finalize_kernel<<<(CV * CN) / 8, 256>>>();
    sg_writeout_kernel<<<1, 1>>>(out);
}